// round 10
// baseline (speedup 1.0000x reference)
#include <cuda_runtime.h>
#include <math.h>

#define NN 50000
#define EE 800000
#define HID 128
#define SROW 132   // padded smem row stride (floats): conflict-free fragment loads
#define SCAN_B 196 // ceil(NN/256)

// ---------------- scratch (device globals; no allocations allowed) ----------
__device__ __align__(16) float    g_xl[NN * HID];      // x @ Wl + bl
__device__ __align__(16) float    g_xr[NN * HID];      // x @ Wr + br
__device__ __align__(16) float    g_accum[NN * HID];   // aggregated attention out
__device__ __align__(16) float    g_logits[EE * 4];    // exp(logit) per edge-head
__device__ int                    g_deg[NN];           // per-node in-degree
__device__ int                    g_off[NN + 1];       // CSR offsets
__device__ int                    g_cur[NN];           // fill cursors
__device__ __align__(8) int2      g_epack[EE];         // (eid, src) grouped by dst
__device__ int                    g_bsum[256];         // scan block sums

// round fp32 -> tf32 (rna), returned as fp32 bit pattern
__device__ __forceinline__ float tf32r(float x) {
    unsigned r;
    asm("cvt.rna.tf32.f32 %0, %1;" : "=r"(r) : "f"(x));
    return __uint_as_float(r);
}

// k-index permutation inside each 8-group: logical (c, c+4) become adjacent,
// so A/B fragment pairs load as one LDS.64
__device__ __forceinline__ int permk(int k) {
    return (k & ~7) | ((k & 3) << 1) | ((k >> 2) & 1);
}

// m16n8k8 tf32 mma, C += A*B
__device__ __forceinline__ void mma8(float* c, const unsigned* a, const unsigned* b) {
    asm volatile(
        "mma.sync.aligned.m16n8k8.row.col.f32.tf32.tf32.f32 "
        "{%0,%1,%2,%3}, {%4,%5,%6,%7}, {%8,%9}, {%0,%1,%2,%3};"
        : "+f"(c[0]), "+f"(c[1]), "+f"(c[2]), "+f"(c[3])
        : "r"(a[0]), "r"(a[1]), "r"(a[2]), "r"(a[3]), "r"(b[0]), "r"(b[1]));
}

// Warp tile M32 x N32 GEMM over K=128 from smem (tf32-prerounded, k-permuted).
__device__ __forceinline__ void warp_gemm2(const float* pA, const float* pB,
                                           float c[2][4][4]) {
#pragma unroll
    for (int ks = 0; ks < 16; ks++) {
        int kb = ks * 8;
        unsigned a[2][4], b[4][2];
#pragma unroll
        for (int mt = 0; mt < 2; mt++) {
            float2 t0 = *(const float2*)(pA + (mt * 16) * SROW + kb);
            float2 t1 = *(const float2*)(pA + (mt * 16 + 8) * SROW + kb);
            a[mt][0] = __float_as_uint(t0.x); a[mt][2] = __float_as_uint(t0.y);
            a[mt][1] = __float_as_uint(t1.x); a[mt][3] = __float_as_uint(t1.y);
        }
#pragma unroll
        for (int nt = 0; nt < 4; nt++) {
            float2 t = *(const float2*)(pB + (nt * 8) * SROW + kb);
            b[nt][0] = __float_as_uint(t.x); b[nt][1] = __float_as_uint(t.y);
        }
#pragma unroll
        for (int mt = 0; mt < 2; mt++)
#pragma unroll
            for (int nt = 0; nt < 4; nt++)
                mma8(c[mt][nt], a[mt], b[nt]);
    }
}

// ---------------- k0: zero degree counters --------------------------------
__global__ void k0_init() {
    int t = blockIdx.x * blockDim.x + threadIdx.x;
    if (t < NN) g_deg[t] = 0;
}

// ---------------- k1: xl = x@Wl+bl, xr = x@Wr+br via tf32 mma -------------
__global__ void __launch_bounds__(512)
k1_mma(const float* __restrict__ x,
       const float* __restrict__ Wl, const float* __restrict__ bl,
       const float* __restrict__ Wr, const float* __restrict__ br) {
    extern __shared__ float sm[];
    float* xs = sm;                 // [128][SROW]
    float* wb = sm + 128 * SROW;    // [128][SROW]
    int tid = threadIdx.x, warp = tid >> 5, lane = tid & 31;
    int wm = warp >> 2, wn = warp & 3;
    int lr = lane >> 2, lc2 = (lane & 3) << 1;
    int row0 = blockIdx.x * 128;

    for (int r = 0; r < 8; r++) {
        int row = warp * 8 + r, node = row0 + row;
        float4 v = make_float4(0.f, 0.f, 0.f, 0.f);
        if (node < NN) v = ((const float4*)x)[node * 32 + lane];
        int c0 = lane * 4;
        xs[row * SROW + permk(c0)]     = tf32r(v.x);
        xs[row * SROW + permk(c0 + 1)] = tf32r(v.y);
        xs[row * SROW + permk(c0 + 2)] = tf32r(v.z);
        xs[row * SROW + permk(c0 + 3)] = tf32r(v.w);
    }

    for (int half = 0; half < 2; half++) {
        const float* W    = half ? Wr : Wl;
        const float* bias = half ? br : bl;
        float* dst        = half ? g_xr : g_xl;
        __syncthreads();
        for (int idx = tid; idx < 128 * 32; idx += 512) {
            int k = idx >> 5, n4 = (idx & 31) << 2;
            float4 w = *(const float4*)(W + k * HID + n4);
            int kp = permk(k);
            wb[(n4 + 0) * SROW + kp] = tf32r(w.x);
            wb[(n4 + 1) * SROW + kp] = tf32r(w.y);
            wb[(n4 + 2) * SROW + kp] = tf32r(w.z);
            wb[(n4 + 3) * SROW + kp] = tf32r(w.w);
        }
        __syncthreads();

        float c[2][4][4];
#pragma unroll
        for (int i = 0; i < 2; i++)
#pragma unroll
            for (int j = 0; j < 4; j++)
#pragma unroll
                for (int e = 0; e < 4; e++) c[i][j][e] = 0.f;

        warp_gemm2(xs + (wm * 32 + lr) * SROW + lc2,
                   wb + (wn * 32 + lr) * SROW + lc2, c);

#pragma unroll
        for (int nt = 0; nt < 4; nt++) {
            int col = wn * 32 + nt * 8 + lc2;
            float b0 = bias[col], b1v = bias[col + 1];
#pragma unroll
            for (int mt = 0; mt < 2; mt++)
#pragma unroll
                for (int h = 0; h < 2; h++) {
                    int node = row0 + wm * 32 + mt * 16 + lr + h * 8;
                    if (node < NN) {
                        float2 o;
                        o.x = c[mt][nt][h * 2] + b0;
                        o.y = c[mt][nt][h * 2 + 1] + b1v;
                        *(float2*)(dst + (size_t)node * HID + col) = o;
                    }
                }
        }
    }
}

// ---------------- k2: per-edge exp(logit) + degree count ------------------
// warp handles 4 consecutive edges; We register-resident (loaded once/warp).
// no-max softmax: logits bounded ~|25|; exp cannot overflow fp32, and
// exp(L)/sum exp(L) == exp(L-max)/sum exp(L-max) mathematically.
__global__ void __launch_bounds__(256)
k2_logits(const int* __restrict__ ei, const float* __restrict__ ea,
          const float* __restrict__ We, const float* __restrict__ att) {
    int lane = threadIdx.x & 31;
    int wg = (blockIdx.x * blockDim.x + threadIdx.x) >> 5;

    // register-resident We slice: w4[k] = We[k][lane*4 .. lane*4+3]
    float4 w4[16];
#pragma unroll
    for (int k = 0; k < 16; k++)
        w4[k] = __ldg(&((const float4*)We)[k * 32 + lane]);
    float4 av = __ldg(&((const float4*)att)[lane]);

    int e0 = wg * 4;
#pragma unroll
    for (int t = 0; t < 4; t++) {
        int e = e0 + t;
        if (e >= EE) return;
        int src = __ldg(&ei[e]);
        int dst = __ldg(&ei[EE + e]);
        float4 xl = ((const float4*)g_xl)[src * 32 + lane];
        float4 xr = ((const float4*)g_xr)[dst * 32 + lane];
        float4 m = make_float4(xl.x + xr.x, xl.y + xr.y,
                               xl.z + xr.z, xl.w + xr.w);
        const float4* eap = (const float4*)(ea + (size_t)e * 16);
#pragma unroll
        for (int q = 0; q < 4; q++) {
            float4 a = __ldg(eap + q);
            float4 w;
            w = w4[4 * q + 0];
            m.x = fmaf(a.x, w.x, m.x); m.y = fmaf(a.x, w.y, m.y);
            m.z = fmaf(a.x, w.z, m.z); m.w = fmaf(a.x, w.w, m.w);
            w = w4[4 * q + 1];
            m.x = fmaf(a.y, w.x, m.x); m.y = fmaf(a.y, w.y, m.y);
            m.z = fmaf(a.y, w.z, m.z); m.w = fmaf(a.y, w.w, m.w);
            w = w4[4 * q + 2];
            m.x = fmaf(a.z, w.x, m.x); m.y = fmaf(a.z, w.y, m.y);
            m.z = fmaf(a.z, w.z, m.z); m.w = fmaf(a.z, w.w, m.w);
            w = w4[4 * q + 3];
            m.x = fmaf(a.w, w.x, m.x); m.y = fmaf(a.w, w.y, m.y);
            m.z = fmaf(a.w, w.z, m.z); m.w = fmaf(a.w, w.w, m.w);
        }
        // LeakyReLU(0.2) == max(x, 0.2x)
        float4 s;
        s.x = fmaxf(m.x, 0.2f * m.x);
        s.y = fmaxf(m.y, 0.2f * m.y);
        s.z = fmaxf(m.z, 0.2f * m.z);
        s.w = fmaxf(m.w, 0.2f * m.w);
        float p = s.x * av.x;
        p = fmaf(s.y, av.y, p);
        p = fmaf(s.z, av.z, p);
        p = fmaf(s.w, av.w, p);
        p += __shfl_xor_sync(0xffffffffu, p, 1);
        p += __shfl_xor_sync(0xffffffffu, p, 2);
        p += __shfl_xor_sync(0xffffffffu, p, 4);
        if ((lane & 7) == 0) {
            g_logits[e * 4 + (lane >> 3)] = expf(p);
        }
        if (lane == 0) atomicAdd(&g_deg[dst], 1);
    }
}

// ---------------- 3-phase grid scan of degrees ----------------------------
__global__ void __launch_bounds__(256) ks1() {
    __shared__ int ws[8];
    int b = blockIdx.x, tx = threadIdx.x;
    int i = b * 256 + tx;
    int v = (i < NN) ? g_deg[i] : 0;
    int lane = tx & 31, w = tx >> 5;
    int s = v;
#pragma unroll
    for (int o = 1; o < 32; o <<= 1) {
        int t = __shfl_up_sync(0xffffffffu, s, o);
        if (lane >= o) s += t;
    }
    if (lane == 31) ws[w] = s;
    __syncthreads();
    if (tx < 8) {
        int t = ws[tx];
#pragma unroll
        for (int o = 1; o < 8; o <<= 1) {
            int u = __shfl_up_sync(0xffu, t, o);
            if (tx >= o) t += u;
        }
        ws[tx] = t;
    }
    __syncthreads();
    int excl = s - v + (w ? ws[w - 1] : 0);
    if (i < NN) g_off[i] = excl;
    if (tx == 255) g_bsum[b] = excl + v;
}

__global__ void __launch_bounds__(256) ks2() {
    __shared__ int ws[8];
    int tx = threadIdx.x;
    int v = (tx < SCAN_B) ? g_bsum[tx] : 0;
    int lane = tx & 31, w = tx >> 5;
    int s = v;
#pragma unroll
    for (int o = 1; o < 32; o <<= 1) {
        int t = __shfl_up_sync(0xffffffffu, s, o);
        if (lane >= o) s += t;
    }
    if (lane == 31) ws[w] = s;
    __syncthreads();
    if (tx < 8) {
        int t = ws[tx];
#pragma unroll
        for (int o = 1; o < 8; o <<= 1) {
            int u = __shfl_up_sync(0xffu, t, o);
            if (tx >= o) t += u;
        }
        ws[tx] = t;
    }
    __syncthreads();
    int excl = s - v + (w ? ws[w - 1] : 0);
    if (tx < SCAN_B) g_bsum[tx] = excl;
    if (tx == 255) g_off[NN] = excl + v;
}

__global__ void __launch_bounds__(256) ks3() {
    int i = blockIdx.x * 256 + threadIdx.x;
    if (i < NN) {
        int o = g_off[i] + g_bsum[blockIdx.x];
        g_off[i] = o;
        g_cur[i] = o;
    }
}

// ---------------- k_fill: bucket (eid, src) by dst -------------------------
__global__ void k_fill(const int* __restrict__ ei) {
    int e = blockIdx.x * blockDim.x + threadIdx.x;
    if (e >= EE) return;
    int src = ei[e];
    int dst = ei[EE + e];
    int pos = atomicAdd(&g_cur[dst], 1);
    g_epack[pos] = make_int2(e, src);
}

// ---------------- k4: per-node softmax-normalize + aggregate --------------
// one warp per node; no atomics, single plain write of the result row
__global__ void k4_agg() {
    int node = (blockIdx.x * blockDim.x + threadIdx.x) >> 5;
    int lane = threadIdx.x & 31;
    if (node >= NN) return;
    int beg = g_off[node], end = g_off[node + 1];

    // pass 1: denominators (4 heads), edges strided across lanes
    float4 den = make_float4(0.f, 0.f, 0.f, 0.f);
    for (int j = beg + lane; j < end; j += 32) {
        int eid = __ldg(&g_epack[j]).x;
        float4 ex = ((const float4*)g_logits)[eid];
        den.x += ex.x; den.y += ex.y; den.z += ex.z; den.w += ex.w;
    }
#pragma unroll
    for (int o = 16; o > 0; o >>= 1) {
        den.x += __shfl_xor_sync(0xffffffffu, den.x, o);
        den.y += __shfl_xor_sync(0xffffffffu, den.y, o);
        den.z += __shfl_xor_sync(0xffffffffu, den.z, o);
        den.w += __shfl_xor_sync(0xffffffffu, den.w, o);
    }
    int h = lane >> 3;
    float denh = (h == 0) ? den.x : (h == 1) ? den.y : (h == 2) ? den.z : den.w;
    float inv = 1.f / (denh + 1e-33f);

    // pass 2: accumulate alpha * xl[src], next-edge prefetch (packed pair)
    float4 acc = make_float4(0.f, 0.f, 0.f, 0.f);
    int2 ep_n = (beg < end) ? __ldg(&g_epack[beg]) : make_int2(0, 0);
    for (int j = beg; j < end; j++) {
        int2 ep = ep_n;
        if (j + 1 < end) ep_n = __ldg(&g_epack[j + 1]);
        float alpha = __ldg(&g_logits[ep.x * 4 + h]) * inv;
        float4 v = ((const float4*)g_xl)[ep.y * 32 + lane];
        acc.x = fmaf(alpha, v.x, acc.x);
        acc.y = fmaf(alpha, v.y, acc.y);
        acc.z = fmaf(alpha, v.z, acc.z);
        acc.w = fmaf(alpha, v.w, acc.w);
    }
    ((float4*)g_accum)[node * 32 + lane] = acc;
}

// ---------------- k5: RMSNorm -> FFN(GELU, tf32 mma) -> RMSNorm -----------
__global__ void __launch_bounds__(512)
k5_mma(const float* __restrict__ x, const float* __restrict__ bias_gat,
       const float* __restrict__ wn1,
       const float* __restrict__ W1, const float* __restrict__ b1,
       const float* __restrict__ W2, const float* __restrict__ b2,
       const float* __restrict__ wn2, float* __restrict__ out) {
    extern __shared__ float sm[];
    float* hs = sm;                  // normed h, tf32, k-permuted
    float* wb = sm + 128 * SROW;     // W1 / W2 chunk, tf32, k-permuted
    float* gb = sm + 2 * 128 * SROW; // gelu output chunk / z buffer
    const float EPS = 1.1920929e-07f;
    const float IS2 = 0.70710678118654752f;
    int tid = threadIdx.x, warp = tid >> 5, lane = tid & 31;
    int wm = warp >> 2, wn = warp & 3;
    int lr = lane >> 2, lc2 = (lane & 3) << 1;
    int row0 = blockIdx.x * 128;

    for (int r = 0; r < 8; r++) {
        int row = warp * 8 + r, node = row0 + row;
        float4 v = make_float4(0.f, 0.f, 0.f, 0.f);
        if (node < NN) {
            float4 xv = ((const float4*)x)[node * 32 + lane];
            float4 av = ((const float4*)g_accum)[node * 32 + lane];
            float4 bg = ((const float4*)bias_gat)[lane];
            v = make_float4(xv.x + av.x + bg.x, xv.y + av.y + bg.y,
                            xv.z + av.z + bg.z, xv.w + av.w + bg.w);
        }
        float ss = v.x * v.x + v.y * v.y + v.z * v.z + v.w * v.w;
#pragma unroll
        for (int o = 16; o > 0; o >>= 1) ss += __shfl_xor_sync(0xffffffffu, ss, o);
        float rs = rsqrtf(ss * (1.f / 128.f) + EPS);
        float4 w = ((const float4*)wn1)[lane];
        int c0 = lane * 4;
        hs[row * SROW + permk(c0)]     = tf32r(v.x * rs * w.x);
        hs[row * SROW + permk(c0 + 1)] = tf32r(v.y * rs * w.y);
        hs[row * SROW + permk(c0 + 2)] = tf32r(v.z * rs * w.z);
        hs[row * SROW + permk(c0 + 3)] = tf32r(v.w * rs * w.w);
    }

    float F[2][4][4];
#pragma unroll
    for (int i = 0; i < 2; i++)
#pragma unroll
        for (int j = 0; j < 4; j++)
#pragma unroll
            for (int e = 0; e < 4; e++) F[i][j][e] = 0.f;

    for (int ci = 0; ci < 4; ci++) {
        int n0 = ci * 128;
        __syncthreads();
        for (int idx = tid; idx < 128 * 32; idx += 512) {
            int k = idx >> 5, n4 = (idx & 31) << 2;
            float4 w = *(const float4*)(W1 + k * 512 + n0 + n4);
            int kp = permk(k);
            wb[(n4 + 0) * SROW + kp] = tf32r(w.x);
            wb[(n4 + 1) * SROW + kp] = tf32r(w.y);
            wb[(n4 + 2) * SROW + kp] = tf32r(w.z);
            wb[(n4 + 3) * SROW + kp] = tf32r(w.w);
        }
        __syncthreads();

        float c1[2][4][4];
#pragma unroll
        for (int i = 0; i < 2; i++)
#pragma unroll
            for (int j = 0; j < 4; j++)
#pragma unroll
                for (int e = 0; e < 4; e++) c1[i][j][e] = 0.f;
        warp_gemm2(hs + (wm * 32 + lr) * SROW + lc2,
                   wb + (wn * 32 + lr) * SROW + lc2, c1);

#pragma unroll
        for (int nt = 0; nt < 4; nt++) {
            int colb = wn * 32 + nt * 8 + lc2;
            float bb0 = b1[n0 + colb], bb1 = b1[n0 + colb + 1];
#pragma unroll
            for (int mt = 0; mt < 2; mt++)
#pragma unroll
                for (int e = 0; e < 4; e++) {
                    float u = c1[mt][nt][e] + ((e & 1) ? bb1 : bb0);
                    float g = 0.5f * u * (1.f + erff(u * IS2));
                    int row = wm * 32 + mt * 16 + lr + ((e >> 1) << 3);
                    int col = colb + (e & 1);
                    gb[row * SROW + permk(col)] = tf32r(g);
                }
        }
        __syncthreads();

        for (int idx = tid; idx < 128 * 32; idx += 512) {
            int k = idx >> 5, o4 = (idx & 31) << 2;
            float4 w = *(const float4*)(W2 + (size_t)(n0 + k) * HID + o4);
            int kp = permk(k);
            wb[(o4 + 0) * SROW + kp] = tf32r(w.x);
            wb[(o4 + 1) * SROW + kp] = tf32r(w.y);
            wb[(o4 + 2) * SROW + kp] = tf32r(w.z);
            wb[(o4 + 3) * SROW + kp] = tf32r(w.w);
        }
        __syncthreads();

        warp_gemm2(gb + (wm * 32 + lr) * SROW + lc2,
                   wb + (wn * 32 + lr) * SROW + lc2, F);
    }
    __syncthreads();

#pragma unroll
    for (int nt = 0; nt < 4; nt++) {
        int col0 = wn * 32 + nt * 8 + lc2;
        float bb0 = b2[col0], bb1 = b2[col0 + 1];
#pragma unroll
        for (int mt = 0; mt < 2; mt++)
#pragma unroll
            for (int e = 0; e < 4; e++) {
                int row = wm * 32 + mt * 16 + lr + ((e >> 1) << 3);
                int col = col0 + (e & 1);
                float z = hs[row * SROW + permk(col)] + F[mt][nt][e]
                          + ((e & 1) ? bb1 : bb0);
                gb[row * SROW + col] = z;
            }
    }
    __syncthreads();

    for (int r = 0; r < 8; r++) {
        int row = warp * 8 + r, node = row0 + row;
        int c0 = lane * 4;
        float z0 = gb[row * SROW + c0];
        float z1 = gb[row * SROW + c0 + 1];
        float z2 = gb[row * SROW + c0 + 2];
        float z3 = gb[row * SROW + c0 + 3];
        float ss = z0 * z0 + z1 * z1 + z2 * z2 + z3 * z3;
#pragma unroll
        for (int o = 16; o > 0; o >>= 1) ss += __shfl_xor_sync(0xffffffffu, ss, o);
        float rs = rsqrtf(ss * (1.f / 128.f) + EPS);
        float4 w = ((const float4*)wn2)[lane];
        if (node < NN) {
            ((float4*)out)[node * 32 + lane] =
                make_float4(z0 * rs * w.x, z1 * rs * w.y,
                            z2 * rs * w.z, z3 * rs * w.w);
        }
    }
}

// ---------------- launch ---------------------------------------------------
extern "C" void kernel_launch(void* const* d_in, const int* in_sizes, int n_in,
                              void* d_out, int out_size) {
    const float* x        = (const float*)d_in[0];
    const int*   ei       = (const int*)  d_in[1];
    const float* ea       = (const float*)d_in[2];
    const float* Wl       = (const float*)d_in[3];
    const float* bl       = (const float*)d_in[4];
    const float* Wr       = (const float*)d_in[5];
    const float* br       = (const float*)d_in[6];
    const float* We       = (const float*)d_in[7];
    const float* att      = (const float*)d_in[8];
    const float* bias_gat = (const float*)d_in[9];
    const float* wn1      = (const float*)d_in[10];
    const float* wn2      = (const float*)d_in[11];
    const float* W1       = (const float*)d_in[12];
    const float* b1       = (const float*)d_in[13];
    const float* W2       = (const float*)d_in[14];
    const float* b2       = (const float*)d_in[15];
    float* out = (float*)d_out;

    const int SM1 = 2 * 128 * SROW * 4;   // 135168 B
    const int SM5 = 3 * 128 * SROW * 4;   // 202752 B
    cudaFuncSetAttribute(k1_mma, cudaFuncAttributeMaxDynamicSharedMemorySize, SM1);
    cudaFuncSetAttribute(k5_mma, cudaFuncAttributeMaxDynamicSharedMemorySize, SM5);

    const int NB = (NN + 127) / 128;      // 391

    k0_init<<<(NN + 255) / 256, 256>>>();
    k1_mma<<<NB, 512, SM1>>>(x, Wl, bl, Wr, br);
    // 8 warps/block, 4 edges/warp -> 32 edges/block
    k2_logits<<<(EE + 31) / 32, 256>>>(ei, ea, We, att);
    ks1<<<SCAN_B, 256>>>();
    ks2<<<1, 256>>>();
    ks3<<<SCAN_B, 256>>>();
    k_fill<<<(EE + 255) / 256, 256>>>(ei);
    k4_agg<<<(NN * 32 + 255) / 256, 256>>>();
    k5_mma<<<NB, 512, SM5>>>(x, bias_gat, wn1, W1, b1, W2, b2, wn2, out);
}

// round 13
// speedup vs baseline: 1.0792x; 1.0792x over previous
#include <cuda_runtime.h>
#include <math.h>

#define NN 50000
#define EE 800000
#define HID 128
#define SROW 132   // padded smem row stride (floats): conflict-free fragment loads
#define SCAN_B 196 // ceil(NN/256)

// ---------------- scratch (device globals; no allocations allowed) ----------
__device__ __align__(16) float    g_xl[NN * HID];      // x @ Wl + bl
__device__ __align__(16) float    g_xr[NN * HID];      // x @ Wr + br
__device__ __align__(16) float    g_accum[NN * HID];   // aggregated attention out
__device__ __align__(16) float    g_logits[EE * 4];    // exp(logit) per edge-head
__device__ int                    g_deg[NN];           // per-node in-degree
__device__ int                    g_off[NN + 1];       // CSR offsets
__device__ int                    g_cur[NN];           // fill cursors
__device__ __align__(8) int2      g_epack[EE];         // (eid, src) grouped by dst
__device__ int                    g_bsum[256];         // scan block sums

// round fp32 -> tf32 (rna), returned as fp32 bit pattern
__device__ __forceinline__ float tf32r(float x) {
    unsigned r;
    asm("cvt.rna.tf32.f32 %0, %1;" : "=r"(r) : "f"(x));
    return __uint_as_float(r);
}

// k-index permutation inside each 8-group: logical (c, c+4) become adjacent,
// so A/B fragment pairs load as one LDS.64
__device__ __forceinline__ int permk(int k) {
    return (k & ~7) | ((k & 3) << 1) | ((k >> 2) & 1);
}

// m16n8k8 tf32 mma, C += A*B
__device__ __forceinline__ void mma8(float* c, const unsigned* a, const unsigned* b) {
    asm volatile(
        "mma.sync.aligned.m16n8k8.row.col.f32.tf32.tf32.f32 "
        "{%0,%1,%2,%3}, {%4,%5,%6,%7}, {%8,%9}, {%0,%1,%2,%3};"
        : "+f"(c[0]), "+f"(c[1]), "+f"(c[2]), "+f"(c[3])
        : "r"(a[0]), "r"(a[1]), "r"(a[2]), "r"(a[3]), "r"(b[0]), "r"(b[1]));
}

// Warp tile M32 x N32 GEMM over K=128 from smem (tf32-prerounded, k-permuted).
__device__ __forceinline__ void warp_gemm2(const float* pA, const float* pB,
                                           float c[2][4][4]) {
#pragma unroll
    for (int ks = 0; ks < 16; ks++) {
        int kb = ks * 8;
        unsigned a[2][4], b[4][2];
#pragma unroll
        for (int mt = 0; mt < 2; mt++) {
            float2 t0 = *(const float2*)(pA + (mt * 16) * SROW + kb);
            float2 t1 = *(const float2*)(pA + (mt * 16 + 8) * SROW + kb);
            a[mt][0] = __float_as_uint(t0.x); a[mt][2] = __float_as_uint(t0.y);
            a[mt][1] = __float_as_uint(t1.x); a[mt][3] = __float_as_uint(t1.y);
        }
#pragma unroll
        for (int nt = 0; nt < 4; nt++) {
            float2 t = *(const float2*)(pB + (nt * 8) * SROW + kb);
            b[nt][0] = __float_as_uint(t.x); b[nt][1] = __float_as_uint(t.y);
        }
#pragma unroll
        for (int mt = 0; mt < 2; mt++)
#pragma unroll
            for (int nt = 0; nt < 4; nt++)
                mma8(c[mt][nt], a[mt], b[nt]);
    }
}

// ---------------- k0: zero degree counters --------------------------------
__global__ void k0_init() {
    int t = blockIdx.x * blockDim.x + threadIdx.x;
    if (t < NN) g_deg[t] = 0;
}

// ---------------- k1: xl = x@Wl+bl, xr = x@Wr+br via tf32 mma -------------
__global__ void __launch_bounds__(512)
k1_mma(const float* __restrict__ x,
       const float* __restrict__ Wl, const float* __restrict__ bl,
       const float* __restrict__ Wr, const float* __restrict__ br) {
    extern __shared__ float sm[];
    float* xs = sm;                 // [128][SROW]
    float* wb = sm + 128 * SROW;    // [128][SROW]
    int tid = threadIdx.x, warp = tid >> 5, lane = tid & 31;
    int wm = warp >> 2, wn = warp & 3;
    int lr = lane >> 2, lc2 = (lane & 3) << 1;
    int row0 = blockIdx.x * 128;

    for (int r = 0; r < 8; r++) {
        int row = warp * 8 + r, node = row0 + row;
        float4 v = make_float4(0.f, 0.f, 0.f, 0.f);
        if (node < NN) v = ((const float4*)x)[node * 32 + lane];
        int c0 = lane * 4;
        xs[row * SROW + permk(c0)]     = tf32r(v.x);
        xs[row * SROW + permk(c0 + 1)] = tf32r(v.y);
        xs[row * SROW + permk(c0 + 2)] = tf32r(v.z);
        xs[row * SROW + permk(c0 + 3)] = tf32r(v.w);
    }

    for (int half = 0; half < 2; half++) {
        const float* W    = half ? Wr : Wl;
        const float* bias = half ? br : bl;
        float* dst        = half ? g_xr : g_xl;
        __syncthreads();
        for (int idx = tid; idx < 128 * 32; idx += 512) {
            int k = idx >> 5, n4 = (idx & 31) << 2;
            float4 w = *(const float4*)(W + k * HID + n4);
            int kp = permk(k);
            wb[(n4 + 0) * SROW + kp] = tf32r(w.x);
            wb[(n4 + 1) * SROW + kp] = tf32r(w.y);
            wb[(n4 + 2) * SROW + kp] = tf32r(w.z);
            wb[(n4 + 3) * SROW + kp] = tf32r(w.w);
        }
        __syncthreads();

        float c[2][4][4];
#pragma unroll
        for (int i = 0; i < 2; i++)
#pragma unroll
            for (int j = 0; j < 4; j++)
#pragma unroll
                for (int e = 0; e < 4; e++) c[i][j][e] = 0.f;

        warp_gemm2(xs + (wm * 32 + lr) * SROW + lc2,
                   wb + (wn * 32 + lr) * SROW + lc2, c);

#pragma unroll
        for (int nt = 0; nt < 4; nt++) {
            int col = wn * 32 + nt * 8 + lc2;
            float b0 = bias[col], b1v = bias[col + 1];
#pragma unroll
            for (int mt = 0; mt < 2; mt++)
#pragma unroll
                for (int h = 0; h < 2; h++) {
                    int node = row0 + wm * 32 + mt * 16 + lr + h * 8;
                    if (node < NN) {
                        float2 o;
                        o.x = c[mt][nt][h * 2] + b0;
                        o.y = c[mt][nt][h * 2 + 1] + b1v;
                        *(float2*)(dst + (size_t)node * HID + col) = o;
                    }
                }
        }
    }
}

// ---------------- k2: per-edge exp(logit) + degree count ------------------
// warp handles TWO edges interleaved: each LDS of We feeds both edges' FMAs
// (halves the smem stream vs 1 edge/warp; no register-resident We table).
// no-max softmax: logits bounded ~|25|; exp cannot overflow fp32, and
// exp(L)/sum exp(L) == exp(L-max)/sum exp(L-max) mathematically.
__global__ void __launch_bounds__(256)
k2_logits(const int* __restrict__ ei, const float* __restrict__ ea,
          const float* __restrict__ We, const float* __restrict__ att) {
    __shared__ __align__(16) float sWe[16 * HID];
    for (int i = threadIdx.x; i < 16 * HID; i += blockDim.x) sWe[i] = We[i];
    __syncthreads();

    int lane = threadIdx.x & 31;
    int wg = (blockIdx.x * blockDim.x + threadIdx.x) >> 5;
    int e0 = wg * 2;                 // EE is even: e0+1 always valid
    if (e0 >= EE) return;

    int src0 = __ldg(&ei[e0]),     dst0 = __ldg(&ei[EE + e0]);
    int src1 = __ldg(&ei[e0 + 1]), dst1 = __ldg(&ei[EE + e0 + 1]);
    float4 xl0 = ((const float4*)g_xl)[src0 * 32 + lane];
    float4 xr0 = ((const float4*)g_xr)[dst0 * 32 + lane];
    float4 xl1 = ((const float4*)g_xl)[src1 * 32 + lane];
    float4 xr1 = ((const float4*)g_xr)[dst1 * 32 + lane];
    float4 m0 = make_float4(xl0.x + xr0.x, xl0.y + xr0.y,
                            xl0.z + xr0.z, xl0.w + xr0.w);
    float4 m1 = make_float4(xl1.x + xr1.x, xl1.y + xr1.y,
                            xl1.z + xr1.z, xl1.w + xr1.w);

    const float4* ea0 = (const float4*)(ea + (size_t)e0 * 16);
    const float4* ea1 = (const float4*)(ea + (size_t)(e0 + 1) * 16);
#pragma unroll
    for (int q = 0; q < 4; q++) {
        float4 a0 = __ldg(ea0 + q);
        float4 a1 = __ldg(ea1 + q);
#pragma unroll
        for (int s = 0; s < 4; s++) {
            float4 w = ((const float4*)sWe)[(4 * q + s) * 32 + lane];
            float c0 = (s == 0) ? a0.x : (s == 1) ? a0.y : (s == 2) ? a0.z : a0.w;
            float c1 = (s == 0) ? a1.x : (s == 1) ? a1.y : (s == 2) ? a1.z : a1.w;
            m0.x = fmaf(c0, w.x, m0.x); m0.y = fmaf(c0, w.y, m0.y);
            m0.z = fmaf(c0, w.z, m0.z); m0.w = fmaf(c0, w.w, m0.w);
            m1.x = fmaf(c1, w.x, m1.x); m1.y = fmaf(c1, w.y, m1.y);
            m1.z = fmaf(c1, w.z, m1.z); m1.w = fmaf(c1, w.w, m1.w);
        }
    }

    float4 av = __ldg(&((const float4*)att)[lane]);
    // LeakyReLU(0.2) == max(x, 0.2x), then dot with att
    float p0, p1;
    {
        float4 s;
        s.x = fmaxf(m0.x, 0.2f * m0.x);
        s.y = fmaxf(m0.y, 0.2f * m0.y);
        s.z = fmaxf(m0.z, 0.2f * m0.z);
        s.w = fmaxf(m0.w, 0.2f * m0.w);
        p0 = s.x * av.x;
        p0 = fmaf(s.y, av.y, p0);
        p0 = fmaf(s.z, av.z, p0);
        p0 = fmaf(s.w, av.w, p0);
    }
    {
        float4 s;
        s.x = fmaxf(m1.x, 0.2f * m1.x);
        s.y = fmaxf(m1.y, 0.2f * m1.y);
        s.z = fmaxf(m1.z, 0.2f * m1.z);
        s.w = fmaxf(m1.w, 0.2f * m1.w);
        p1 = s.x * av.x;
        p1 = fmaf(s.y, av.y, p1);
        p1 = fmaf(s.z, av.z, p1);
        p1 = fmaf(s.w, av.w, p1);
    }
    // reduce within each 8-lane head group (both edges)
    p0 += __shfl_xor_sync(0xffffffffu, p0, 1);
    p1 += __shfl_xor_sync(0xffffffffu, p1, 1);
    p0 += __shfl_xor_sync(0xffffffffu, p0, 2);
    p1 += __shfl_xor_sync(0xffffffffu, p1, 2);
    p0 += __shfl_xor_sync(0xffffffffu, p0, 4);
    p1 += __shfl_xor_sync(0xffffffffu, p1, 4);
    if ((lane & 7) == 0) {
        int h = lane >> 3;
        g_logits[e0 * 4 + h]       = expf(p0);
        g_logits[(e0 + 1) * 4 + h] = expf(p1);
    }
    if (lane == 0) {
        atomicAdd(&g_deg[dst0], 1);
        atomicAdd(&g_deg[dst1], 1);
    }
}

// ---------------- 3-phase grid scan of degrees ----------------------------
__global__ void __launch_bounds__(256) ks1() {
    __shared__ int ws[8];
    int b = blockIdx.x, tx = threadIdx.x;
    int i = b * 256 + tx;
    int v = (i < NN) ? g_deg[i] : 0;
    int lane = tx & 31, w = tx >> 5;
    int s = v;
#pragma unroll
    for (int o = 1; o < 32; o <<= 1) {
        int t = __shfl_up_sync(0xffffffffu, s, o);
        if (lane >= o) s += t;
    }
    if (lane == 31) ws[w] = s;
    __syncthreads();
    if (tx < 8) {
        int t = ws[tx];
#pragma unroll
        for (int o = 1; o < 8; o <<= 1) {
            int u = __shfl_up_sync(0xffu, t, o);
            if (tx >= o) t += u;
        }
        ws[tx] = t;
    }
    __syncthreads();
    int excl = s - v + (w ? ws[w - 1] : 0);
    if (i < NN) g_off[i] = excl;
    if (tx == 255) g_bsum[b] = excl + v;
}

__global__ void __launch_bounds__(256) ks2() {
    __shared__ int ws[8];
    int tx = threadIdx.x;
    int v = (tx < SCAN_B) ? g_bsum[tx] : 0;
    int lane = tx & 31, w = tx >> 5;
    int s = v;
#pragma unroll
    for (int o = 1; o < 32; o <<= 1) {
        int t = __shfl_up_sync(0xffffffffu, s, o);
        if (lane >= o) s += t;
    }
    if (lane == 31) ws[w] = s;
    __syncthreads();
    if (tx < 8) {
        int t = ws[tx];
#pragma unroll
        for (int o = 1; o < 8; o <<= 1) {
            int u = __shfl_up_sync(0xffu, t, o);
            if (tx >= o) t += u;
        }
        ws[tx] = t;
    }
    __syncthreads();
    int excl = s - v + (w ? ws[w - 1] : 0);
    if (tx < SCAN_B) g_bsum[tx] = excl;
    if (tx == 255) g_off[NN] = excl + v;
}

__global__ void __launch_bounds__(256) ks3() {
    int i = blockIdx.x * 256 + threadIdx.x;
    if (i < NN) {
        int o = g_off[i] + g_bsum[blockIdx.x];
        g_off[i] = o;
        g_cur[i] = o;
    }
}

// ---------------- k_fill: bucket (eid, src) by dst -------------------------
__global__ void k_fill(const int* __restrict__ ei) {
    int e = blockIdx.x * blockDim.x + threadIdx.x;
    if (e >= EE) return;
    int src = ei[e];
    int dst = ei[EE + e];
    int pos = atomicAdd(&g_cur[dst], 1);
    g_epack[pos] = make_int2(e, src);
}

// ---------------- k4: per-node softmax-normalize + aggregate --------------
// one warp per node; no atomics, single plain write of the result row
__global__ void k4_agg() {
    int node = (blockIdx.x * blockDim.x + threadIdx.x) >> 5;
    int lane = threadIdx.x & 31;
    if (node >= NN) return;
    int beg = g_off[node], end = g_off[node + 1];

    // pass 1: denominators (4 heads), edges strided across lanes
    float4 den = make_float4(0.f, 0.f, 0.f, 0.f);
    for (int j = beg + lane; j < end; j += 32) {
        int eid = __ldg(&g_epack[j]).x;
        float4 ex = ((const float4*)g_logits)[eid];
        den.x += ex.x; den.y += ex.y; den.z += ex.z; den.w += ex.w;
    }
#pragma unroll
    for (int o = 16; o > 0; o >>= 1) {
        den.x += __shfl_xor_sync(0xffffffffu, den.x, o);
        den.y += __shfl_xor_sync(0xffffffffu, den.y, o);
        den.z += __shfl_xor_sync(0xffffffffu, den.z, o);
        den.w += __shfl_xor_sync(0xffffffffu, den.w, o);
    }
    int h = lane >> 3;
    float denh = (h == 0) ? den.x : (h == 1) ? den.y : (h == 2) ? den.z : den.w;
    float inv = 1.f / (denh + 1e-33f);

    // pass 2: accumulate alpha * xl[src], next-edge prefetch (packed pair)
    float4 acc = make_float4(0.f, 0.f, 0.f, 0.f);
    int2 ep_n = (beg < end) ? __ldg(&g_epack[beg]) : make_int2(0, 0);
    for (int j = beg; j < end; j++) {
        int2 ep = ep_n;
        if (j + 1 < end) ep_n = __ldg(&g_epack[j + 1]);
        float alpha = __ldg(&g_logits[ep.x * 4 + h]) * inv;
        float4 v = ((const float4*)g_xl)[ep.y * 32 + lane];
        acc.x = fmaf(alpha, v.x, acc.x);
        acc.y = fmaf(alpha, v.y, acc.y);
        acc.z = fmaf(alpha, v.z, acc.z);
        acc.w = fmaf(alpha, v.w, acc.w);
    }
    ((float4*)g_accum)[node * 32 + lane] = acc;
}

// ---------------- k5: RMSNorm -> FFN(GELU, tf32 mma) -> RMSNorm -----------
__global__ void __launch_bounds__(512)
k5_mma(const float* __restrict__ x, const float* __restrict__ bias_gat,
       const float* __restrict__ wn1,
       const float* __restrict__ W1, const float* __restrict__ b1,
       const float* __restrict__ W2, const float* __restrict__ b2,
       const float* __restrict__ wn2, float* __restrict__ out) {
    extern __shared__ float sm[];
    float* hs = sm;                  // normed h, tf32, k-permuted
    float* wb = sm + 128 * SROW;     // W1 / W2 chunk, tf32, k-permuted
    float* gb = sm + 2 * 128 * SROW; // gelu output chunk / z buffer
    const float EPS = 1.1920929e-07f;
    const float IS2 = 0.70710678118654752f;
    int tid = threadIdx.x, warp = tid >> 5, lane = tid & 31;
    int wm = warp >> 2, wn = warp & 3;
    int lr = lane >> 2, lc2 = (lane & 3) << 1;
    int row0 = blockIdx.x * 128;

    for (int r = 0; r < 8; r++) {
        int row = warp * 8 + r, node = row0 + row;
        float4 v = make_float4(0.f, 0.f, 0.f, 0.f);
        if (node < NN) {
            float4 xv = ((const float4*)x)[node * 32 + lane];
            float4 av = ((const float4*)g_accum)[node * 32 + lane];
            float4 bg = ((const float4*)bias_gat)[lane];
            v = make_float4(xv.x + av.x + bg.x, xv.y + av.y + bg.y,
                            xv.z + av.z + bg.z, xv.w + av.w + bg.w);
        }
        float ss = v.x * v.x + v.y * v.y + v.z * v.z + v.w * v.w;
#pragma unroll
        for (int o = 16; o > 0; o >>= 1) ss += __shfl_xor_sync(0xffffffffu, ss, o);
        float rs = rsqrtf(ss * (1.f / 128.f) + EPS);
        float4 w = ((const float4*)wn1)[lane];
        int c0 = lane * 4;
        hs[row * SROW + permk(c0)]     = tf32r(v.x * rs * w.x);
        hs[row * SROW + permk(c0 + 1)] = tf32r(v.y * rs * w.y);
        hs[row * SROW + permk(c0 + 2)] = tf32r(v.z * rs * w.z);
        hs[row * SROW + permk(c0 + 3)] = tf32r(v.w * rs * w.w);
    }

    float F[2][4][4];
#pragma unroll
    for (int i = 0; i < 2; i++)
#pragma unroll
        for (int j = 0; j < 4; j++)
#pragma unroll
            for (int e = 0; e < 4; e++) F[i][j][e] = 0.f;

    for (int ci = 0; ci < 4; ci++) {
        int n0 = ci * 128;
        __syncthreads();
        for (int idx = tid; idx < 128 * 32; idx += 512) {
            int k = idx >> 5, n4 = (idx & 31) << 2;
            float4 w = *(const float4*)(W1 + k * 512 + n0 + n4);
            int kp = permk(k);
            wb[(n4 + 0) * SROW + kp] = tf32r(w.x);
            wb[(n4 + 1) * SROW + kp] = tf32r(w.y);
            wb[(n4 + 2) * SROW + kp] = tf32r(w.z);
            wb[(n4 + 3) * SROW + kp] = tf32r(w.w);
        }
        __syncthreads();

        float c1[2][4][4];
#pragma unroll
        for (int i = 0; i < 2; i++)
#pragma unroll
            for (int j = 0; j < 4; j++)
#pragma unroll
                for (int e = 0; e < 4; e++) c1[i][j][e] = 0.f;
        warp_gemm2(hs + (wm * 32 + lr) * SROW + lc2,
                   wb + (wn * 32 + lr) * SROW + lc2, c1);

#pragma unroll
        for (int nt = 0; nt < 4; nt++) {
            int colb = wn * 32 + nt * 8 + lc2;
            float bb0 = b1[n0 + colb], bb1 = b1[n0 + colb + 1];
#pragma unroll
            for (int mt = 0; mt < 2; mt++)
#pragma unroll
                for (int e = 0; e < 4; e++) {
                    float u = c1[mt][nt][e] + ((e & 1) ? bb1 : bb0);
                    float g = 0.5f * u * (1.f + erff(u * IS2));
                    int row = wm * 32 + mt * 16 + lr + ((e >> 1) << 3);
                    int col = colb + (e & 1);
                    gb[row * SROW + permk(col)] = tf32r(g);
                }
        }
        __syncthreads();

        for (int idx = tid; idx < 128 * 32; idx += 512) {
            int k = idx >> 5, o4 = (idx & 31) << 2;
            float4 w = *(const float4*)(W2 + (size_t)(n0 + k) * HID + o4);
            int kp = permk(k);
            wb[(o4 + 0) * SROW + kp] = tf32r(w.x);
            wb[(o4 + 1) * SROW + kp] = tf32r(w.y);
            wb[(o4 + 2) * SROW + kp] = tf32r(w.z);
            wb[(o4 + 3) * SROW + kp] = tf32r(w.w);
        }
        __syncthreads();

        warp_gemm2(gb + (wm * 32 + lr) * SROW + lc2,
                   wb + (wn * 32 + lr) * SROW + lc2, F);
    }
    __syncthreads();

#pragma unroll
    for (int nt = 0; nt < 4; nt++) {
        int col0 = wn * 32 + nt * 8 + lc2;
        float bb0 = b2[col0], bb1 = b2[col0 + 1];
#pragma unroll
        for (int mt = 0; mt < 2; mt++)
#pragma unroll
            for (int e = 0; e < 4; e++) {
                int row = wm * 32 + mt * 16 + lr + ((e >> 1) << 3);
                int col = col0 + (e & 1);
                float z = hs[row * SROW + permk(col)] + F[mt][nt][e]
                          + ((e & 1) ? bb1 : bb0);
                gb[row * SROW + col] = z;
            }
    }
    __syncthreads();

    for (int r = 0; r < 8; r++) {
        int row = warp * 8 + r, node = row0 + row;
        int c0 = lane * 4;
        float z0 = gb[row * SROW + c0];
        float z1 = gb[row * SROW + c0 + 1];
        float z2 = gb[row * SROW + c0 + 2];
        float z3 = gb[row * SROW + c0 + 3];
        float ss = z0 * z0 + z1 * z1 + z2 * z2 + z3 * z3;
#pragma unroll
        for (int o = 16; o > 0; o >>= 1) ss += __shfl_xor_sync(0xffffffffu, ss, o);
        float rs = rsqrtf(ss * (1.f / 128.f) + EPS);
        float4 w = ((const float4*)wn2)[lane];
        if (node < NN) {
            ((float4*)out)[node * 32 + lane] =
                make_float4(z0 * rs * w.x, z1 * rs * w.y,
                            z2 * rs * w.z, z3 * rs * w.w);
        }
    }
}

// ---------------- launch ---------------------------------------------------
extern "C" void kernel_launch(void* const* d_in, const int* in_sizes, int n_in,
                              void* d_out, int out_size) {
    const float* x        = (const float*)d_in[0];
    const int*   ei       = (const int*)  d_in[1];
    const float* ea       = (const float*)d_in[2];
    const float* Wl       = (const float*)d_in[3];
    const float* bl       = (const float*)d_in[4];
    const float* Wr       = (const float*)d_in[5];
    const float* br       = (const float*)d_in[6];
    const float* We       = (const float*)d_in[7];
    const float* att      = (const float*)d_in[8];
    const float* bias_gat = (const float*)d_in[9];
    const float* wn1      = (const float*)d_in[10];
    const float* wn2      = (const float*)d_in[11];
    const float* W1       = (const float*)d_in[12];
    const float* b1       = (const float*)d_in[13];
    const float* W2       = (const float*)d_in[14];
    const float* b2       = (const float*)d_in[15];
    float* out = (float*)d_out;

    const int SM1 = 2 * 128 * SROW * 4;   // 135168 B
    const int SM5 = 3 * 128 * SROW * 4;   // 202752 B
    cudaFuncSetAttribute(k1_mma, cudaFuncAttributeMaxDynamicSharedMemorySize, SM1);
    cudaFuncSetAttribute(k5_mma, cudaFuncAttributeMaxDynamicSharedMemorySize, SM5);

    const int NB = (NN + 127) / 128;      // 391

    k0_init<<<(NN + 255) / 256, 256>>>();
    k1_mma<<<NB, 512, SM1>>>(x, Wl, bl, Wr, br);
    // 8 warps/block, 2 edges/warp -> 16 edges/block
    k2_logits<<<(EE + 15) / 16, 256>>>(ei, ea, We, att);
    ks1<<<SCAN_B, 256>>>();
    ks2<<<1, 256>>>();
    ks3<<<SCAN_B, 256>>>();
    k_fill<<<(EE + 255) / 256, 256>>>(ei);
    k4_agg<<<(NN * 32 + 255) / 256, 256>>>();
    k5_mma<<<NB, 512, SM5>>>(x, bias_gat, wn1, W1, b1, W2, b2, wn2, out);
}

// round 16
// speedup vs baseline: 1.4027x; 1.2998x over previous
#include <cuda_runtime.h>
#include <math.h>

#define NN 50000
#define EE 800000
#define HID 128
#define SROW 132   // padded smem row stride (floats): conflict-free fragment loads
#define SCAN_B 196 // ceil(NN/256)

// ---------------- scratch (device globals; no allocations allowed) ----------
__device__ __align__(16) float    g_xl[NN * HID];      // x @ Wl + bl
__device__ __align__(16) float    g_xr[NN * HID];      // x @ Wr + br
__device__ __align__(16) float    g_accum[NN * HID];   // aggregated attention out
__device__ __align__(16) float    g_logits[EE * 4];    // exp(logit), CSR-ordered
__device__ int                    g_deg[NN];           // per-node in-degree
__device__ int                    g_off[NN + 1];       // CSR offsets
__device__ int                    g_cur[NN];           // fill cursors
__device__ int                    g_pos[EE];           // edge -> CSR slot
__device__ int                    g_srcs[EE];          // CSR slot -> src node
__device__ int                    g_bsum[256];         // scan block sums

// round fp32 -> tf32 (rna), returned as fp32 bit pattern
__device__ __forceinline__ float tf32r(float x) {
    unsigned r;
    asm("cvt.rna.tf32.f32 %0, %1;" : "=r"(r) : "f"(x));
    return __uint_as_float(r);
}

// k-index permutation inside each 8-group: logical (c, c+4) become adjacent,
// so A/B fragment pairs load as one LDS.64
__device__ __forceinline__ int permk(int k) {
    return (k & ~7) | ((k & 3) << 1) | ((k >> 2) & 1);
}

// m16n8k8 tf32 mma, C += A*B
__device__ __forceinline__ void mma8(float* c, const unsigned* a, const unsigned* b) {
    asm volatile(
        "mma.sync.aligned.m16n8k8.row.col.f32.tf32.tf32.f32 "
        "{%0,%1,%2,%3}, {%4,%5,%6,%7}, {%8,%9}, {%0,%1,%2,%3};"
        : "+f"(c[0]), "+f"(c[1]), "+f"(c[2]), "+f"(c[3])
        : "r"(a[0]), "r"(a[1]), "r"(a[2]), "r"(a[3]), "r"(b[0]), "r"(b[1]));
}

// Warp tile M32 x N32 GEMM over K=128 from smem (tf32-prerounded, k-permuted).
__device__ __forceinline__ void warp_gemm2(const float* pA, const float* pB,
                                           float c[2][4][4]) {
#pragma unroll
    for (int ks = 0; ks < 16; ks++) {
        int kb = ks * 8;
        unsigned a[2][4], b[4][2];
#pragma unroll
        for (int mt = 0; mt < 2; mt++) {
            float2 t0 = *(const float2*)(pA + (mt * 16) * SROW + kb);
            float2 t1 = *(const float2*)(pA + (mt * 16 + 8) * SROW + kb);
            a[mt][0] = __float_as_uint(t0.x); a[mt][2] = __float_as_uint(t0.y);
            a[mt][1] = __float_as_uint(t1.x); a[mt][3] = __float_as_uint(t1.y);
        }
#pragma unroll
        for (int nt = 0; nt < 4; nt++) {
            float2 t = *(const float2*)(pB + (nt * 8) * SROW + kb);
            b[nt][0] = __float_as_uint(t.x); b[nt][1] = __float_as_uint(t.y);
        }
#pragma unroll
        for (int mt = 0; mt < 2; mt++)
#pragma unroll
            for (int nt = 0; nt < 4; nt++)
                mma8(c[mt][nt], a[mt], b[nt]);
    }
}

// ---------------- k0: zero degree counters --------------------------------
__global__ void k0_init() {
    int t = blockIdx.x * blockDim.x + threadIdx.x;
    if (t < NN) g_deg[t] = 0;
}

// ---------------- kd: count in-degrees ------------------------------------
__global__ void kd_count(const int* __restrict__ ei) {
    int e = blockIdx.x * blockDim.x + threadIdx.x;
    if (e < EE) atomicAdd(&g_deg[__ldg(&ei[EE + e])], 1);
}

// ---------------- k1: xl = x@Wl+bl, xr = x@Wr+br via tf32 mma -------------
__global__ void __launch_bounds__(512)
k1_mma(const float* __restrict__ x,
       const float* __restrict__ Wl, const float* __restrict__ bl,
       const float* __restrict__ Wr, const float* __restrict__ br) {
    extern __shared__ float sm[];
    float* xs = sm;                 // [128][SROW]
    float* wb = sm + 128 * SROW;    // [128][SROW]
    int tid = threadIdx.x, warp = tid >> 5, lane = tid & 31;
    int wm = warp >> 2, wn = warp & 3;
    int lr = lane >> 2, lc2 = (lane & 3) << 1;
    int row0 = blockIdx.x * 128;

    for (int r = 0; r < 8; r++) {
        int row = warp * 8 + r, node = row0 + row;
        float4 v = make_float4(0.f, 0.f, 0.f, 0.f);
        if (node < NN) v = ((const float4*)x)[node * 32 + lane];
        int c0 = lane * 4;
        xs[row * SROW + permk(c0)]     = tf32r(v.x);
        xs[row * SROW + permk(c0 + 1)] = tf32r(v.y);
        xs[row * SROW + permk(c0 + 2)] = tf32r(v.z);
        xs[row * SROW + permk(c0 + 3)] = tf32r(v.w);
    }

    for (int half = 0; half < 2; half++) {
        const float* W    = half ? Wr : Wl;
        const float* bias = half ? br : bl;
        float* dst        = half ? g_xr : g_xl;
        __syncthreads();
        for (int idx = tid; idx < 128 * 32; idx += 512) {
            int k = idx >> 5, n4 = (idx & 31) << 2;
            float4 w = *(const float4*)(W + k * HID + n4);
            int kp = permk(k);
            wb[(n4 + 0) * SROW + kp] = tf32r(w.x);
            wb[(n4 + 1) * SROW + kp] = tf32r(w.y);
            wb[(n4 + 2) * SROW + kp] = tf32r(w.z);
            wb[(n4 + 3) * SROW + kp] = tf32r(w.w);
        }
        __syncthreads();

        float c[2][4][4];
#pragma unroll
        for (int i = 0; i < 2; i++)
#pragma unroll
            for (int j = 0; j < 4; j++)
#pragma unroll
                for (int e = 0; e < 4; e++) c[i][j][e] = 0.f;

        warp_gemm2(xs + (wm * 32 + lr) * SROW + lc2,
                   wb + (wn * 32 + lr) * SROW + lc2, c);

#pragma unroll
        for (int nt = 0; nt < 4; nt++) {
            int col = wn * 32 + nt * 8 + lc2;
            float b0 = bias[col], b1v = bias[col + 1];
#pragma unroll
            for (int mt = 0; mt < 2; mt++)
#pragma unroll
                for (int h = 0; h < 2; h++) {
                    int node = row0 + wm * 32 + mt * 16 + lr + h * 8;
                    if (node < NN) {
                        float2 o;
                        o.x = c[mt][nt][h * 2] + b0;
                        o.y = c[mt][nt][h * 2 + 1] + b1v;
                        *(float2*)(dst + (size_t)node * HID + col) = o;
                    }
                }
        }
    }
}

// ---------------- 3-phase grid scan of degrees ----------------------------
__global__ void __launch_bounds__(256) ks1() {
    __shared__ int ws[8];
    int b = blockIdx.x, tx = threadIdx.x;
    int i = b * 256 + tx;
    int v = (i < NN) ? g_deg[i] : 0;
    int lane = tx & 31, w = tx >> 5;
    int s = v;
#pragma unroll
    for (int o = 1; o < 32; o <<= 1) {
        int t = __shfl_up_sync(0xffffffffu, s, o);
        if (lane >= o) s += t;
    }
    if (lane == 31) ws[w] = s;
    __syncthreads();
    if (tx < 8) {
        int t = ws[tx];
#pragma unroll
        for (int o = 1; o < 8; o <<= 1) {
            int u = __shfl_up_sync(0xffu, t, o);
            if (tx >= o) t += u;
        }
        ws[tx] = t;
    }
    __syncthreads();
    int excl = s - v + (w ? ws[w - 1] : 0);
    if (i < NN) g_off[i] = excl;
    if (tx == 255) g_bsum[b] = excl + v;
}

__global__ void __launch_bounds__(256) ks2() {
    __shared__ int ws[8];
    int tx = threadIdx.x;
    int v = (tx < SCAN_B) ? g_bsum[tx] : 0;
    int lane = tx & 31, w = tx >> 5;
    int s = v;
#pragma unroll
    for (int o = 1; o < 32; o <<= 1) {
        int t = __shfl_up_sync(0xffffffffu, s, o);
        if (lane >= o) s += t;
    }
    if (lane == 31) ws[w] = s;
    __syncthreads();
    if (tx < 8) {
        int t = ws[tx];
#pragma unroll
        for (int o = 1; o < 8; o <<= 1) {
            int u = __shfl_up_sync(0xffu, t, o);
            if (tx >= o) t += u;
        }
        ws[tx] = t;
    }
    __syncthreads();
    int excl = s - v + (w ? ws[w - 1] : 0);
    if (tx < SCAN_B) g_bsum[tx] = excl;
    if (tx == 255) g_off[NN] = excl + v;
}

__global__ void __launch_bounds__(256) ks3() {
    int i = blockIdx.x * 256 + threadIdx.x;
    if (i < NN) {
        int o = g_off[i] + g_bsum[blockIdx.x];
        g_off[i] = o;
        g_cur[i] = o;
    }
}

// ---------------- k_fill: assign CSR slots --------------------------------
// g_pos[e] = slot; g_srcs[slot] = src   (runs BEFORE k2 now)
__global__ void k_fill(const int* __restrict__ ei) {
    int e = blockIdx.x * blockDim.x + threadIdx.x;
    if (e >= EE) return;
    int src = __ldg(&ei[e]);
    int dst = __ldg(&ei[EE + e]);
    int pos = atomicAdd(&g_cur[dst], 1);
    g_pos[e] = pos;
    g_srcs[pos] = src;
}

// ---------------- k2: per-edge exp(logit), written in CSR order -----------
// one warp per edge (round-8 shape); no-max softmax: logits bounded ~|25|,
// exp cannot overflow fp32, and exp(L)/sum == exp(L-max)/sum(L-max).
__global__ void k2_logits(const int* __restrict__ ei, const float* __restrict__ ea,
                          const float* __restrict__ We, const float* __restrict__ att) {
    __shared__ __align__(16) float sWe[16 * HID];
    for (int i = threadIdx.x; i < 16 * HID; i += blockDim.x) sWe[i] = We[i];
    __syncthreads();

    int e = (blockIdx.x * blockDim.x + threadIdx.x) >> 5;
    int lane = threadIdx.x & 31;
    if (e >= EE) return;

    int src = __ldg(&ei[e]);
    int dst = __ldg(&ei[EE + e]);
    float4 xl = ((const float4*)g_xl)[src * 32 + lane];
    float4 xr = ((const float4*)g_xr)[dst * 32 + lane];
    float4 m = make_float4(xl.x + xr.x, xl.y + xr.y, xl.z + xr.z, xl.w + xr.w);

    const float* eap = ea + (size_t)e * 16;
#pragma unroll
    for (int k = 0; k < 16; k++) {
        float a = __ldg(eap + k);
        float4 w = ((const float4*)sWe)[k * 32 + lane];
        m.x = fmaf(a, w.x, m.x);
        m.y = fmaf(a, w.y, m.y);
        m.z = fmaf(a, w.z, m.z);
        m.w = fmaf(a, w.w, m.w);
    }
    float4 s;
    s.x = fmaxf(m.x, 0.2f * m.x);
    s.y = fmaxf(m.y, 0.2f * m.y);
    s.z = fmaxf(m.z, 0.2f * m.z);
    s.w = fmaxf(m.w, 0.2f * m.w);

    float4 av = __ldg(&((const float4*)att)[lane]);
    float p = s.x * av.x;
    p = fmaf(s.y, av.y, p);
    p = fmaf(s.z, av.z, p);
    p = fmaf(s.w, av.w, p);
    p += __shfl_xor_sync(0xffffffffu, p, 1);
    p += __shfl_xor_sync(0xffffffffu, p, 2);
    p += __shfl_xor_sync(0xffffffffu, p, 4);
    if ((lane & 7) == 0) {
        int pos = __ldg(&g_pos[e]);
        g_logits[pos * 4 + (lane >> 3)] = expf(p);
    }
}

// ---------------- k4: per-node softmax-normalize + aggregate --------------
// one warp per node; logits & srcs now CSR-contiguous (no eid indirection)
__global__ void k4_agg() {
    int node = (blockIdx.x * blockDim.x + threadIdx.x) >> 5;
    int lane = threadIdx.x & 31;
    if (node >= NN) return;
    int beg = g_off[node], end = g_off[node + 1];

    // pass 1: denominators (4 heads), fully sequential float4 stream
    float4 den = make_float4(0.f, 0.f, 0.f, 0.f);
    for (int j = beg + lane; j < end; j += 32) {
        float4 ex = __ldg(&((const float4*)g_logits)[j]);
        den.x += ex.x; den.y += ex.y; den.z += ex.z; den.w += ex.w;
    }
#pragma unroll
    for (int o = 16; o > 0; o >>= 1) {
        den.x += __shfl_xor_sync(0xffffffffu, den.x, o);
        den.y += __shfl_xor_sync(0xffffffffu, den.y, o);
        den.z += __shfl_xor_sync(0xffffffffu, den.z, o);
        den.w += __shfl_xor_sync(0xffffffffu, den.w, o);
    }
    int h = lane >> 3;
    float denh = (h == 0) ? den.x : (h == 1) ? den.y : (h == 2) ? den.z : den.w;
    float inv = 1.f / (denh + 1e-33f);

    // pass 2: accumulate alpha * xl[src]; alpha & src reads are sequential,
    // next-src prefetch breaks the gather chain
    float4 acc = make_float4(0.f, 0.f, 0.f, 0.f);
    int src_n = (beg < end) ? __ldg(&g_srcs[beg]) : 0;
    for (int j = beg; j < end; j++) {
        int src = src_n;
        if (j + 1 < end) src_n = __ldg(&g_srcs[j + 1]);
        float alpha = __ldg(&g_logits[j * 4 + h]) * inv;
        float4 v = ((const float4*)g_xl)[src * 32 + lane];
        acc.x = fmaf(alpha, v.x, acc.x);
        acc.y = fmaf(alpha, v.y, acc.y);
        acc.z = fmaf(alpha, v.z, acc.z);
        acc.w = fmaf(alpha, v.w, acc.w);
    }
    ((float4*)g_accum)[node * 32 + lane] = acc;
}

// ---------------- k5: RMSNorm -> FFN(GELU, tf32 mma) -> RMSNorm -----------
__global__ void __launch_bounds__(512)
k5_mma(const float* __restrict__ x, const float* __restrict__ bias_gat,
       const float* __restrict__ wn1,
       const float* __restrict__ W1, const float* __restrict__ b1,
       const float* __restrict__ W2, const float* __restrict__ b2,
       const float* __restrict__ wn2, float* __restrict__ out) {
    extern __shared__ float sm[];
    float* hs = sm;                  // normed h, tf32, k-permuted
    float* wb = sm + 128 * SROW;     // W1 / W2 chunk, tf32, k-permuted
    float* gb = sm + 2 * 128 * SROW; // gelu output chunk / z buffer
    const float EPS = 1.1920929e-07f;
    const float IS2 = 0.70710678118654752f;
    int tid = threadIdx.x, warp = tid >> 5, lane = tid & 31;
    int wm = warp >> 2, wn = warp & 3;
    int lr = lane >> 2, lc2 = (lane & 3) << 1;
    int row0 = blockIdx.x * 128;

    for (int r = 0; r < 8; r++) {
        int row = warp * 8 + r, node = row0 + row;
        float4 v = make_float4(0.f, 0.f, 0.f, 0.f);
        if (node < NN) {
            float4 xv = ((const float4*)x)[node * 32 + lane];
            float4 av = ((const float4*)g_accum)[node * 32 + lane];
            float4 bg = ((const float4*)bias_gat)[lane];
            v = make_float4(xv.x + av.x + bg.x, xv.y + av.y + bg.y,
                            xv.z + av.z + bg.z, xv.w + av.w + bg.w);
        }
        float ss = v.x * v.x + v.y * v.y + v.z * v.z + v.w * v.w;
#pragma unroll
        for (int o = 16; o > 0; o >>= 1) ss += __shfl_xor_sync(0xffffffffu, ss, o);
        float rs = rsqrtf(ss * (1.f / 128.f) + EPS);
        float4 w = ((const float4*)wn1)[lane];
        int c0 = lane * 4;
        hs[row * SROW + permk(c0)]     = tf32r(v.x * rs * w.x);
        hs[row * SROW + permk(c0 + 1)] = tf32r(v.y * rs * w.y);
        hs[row * SROW + permk(c0 + 2)] = tf32r(v.z * rs * w.z);
        hs[row * SROW + permk(c0 + 3)] = tf32r(v.w * rs * w.w);
    }

    float F[2][4][4];
#pragma unroll
    for (int i = 0; i < 2; i++)
#pragma unroll
        for (int j = 0; j < 4; j++)
#pragma unroll
            for (int e = 0; e < 4; e++) F[i][j][e] = 0.f;

    for (int ci = 0; ci < 4; ci++) {
        int n0 = ci * 128;
        __syncthreads();
        for (int idx = tid; idx < 128 * 32; idx += 512) {
            int k = idx >> 5, n4 = (idx & 31) << 2;
            float4 w = *(const float4*)(W1 + k * 512 + n0 + n4);
            int kp = permk(k);
            wb[(n4 + 0) * SROW + kp] = tf32r(w.x);
            wb[(n4 + 1) * SROW + kp] = tf32r(w.y);
            wb[(n4 + 2) * SROW + kp] = tf32r(w.z);
            wb[(n4 + 3) * SROW + kp] = tf32r(w.w);
        }
        __syncthreads();

        float c1[2][4][4];
#pragma unroll
        for (int i = 0; i < 2; i++)
#pragma unroll
            for (int j = 0; j < 4; j++)
#pragma unroll
                for (int e = 0; e < 4; e++) c1[i][j][e] = 0.f;
        warp_gemm2(hs + (wm * 32 + lr) * SROW + lc2,
                   wb + (wn * 32 + lr) * SROW + lc2, c1);

#pragma unroll
        for (int nt = 0; nt < 4; nt++) {
            int colb = wn * 32 + nt * 8 + lc2;
            float bb0 = b1[n0 + colb], bb1 = b1[n0 + colb + 1];
#pragma unroll
            for (int mt = 0; mt < 2; mt++)
#pragma unroll
                for (int e = 0; e < 4; e++) {
                    float u = c1[mt][nt][e] + ((e & 1) ? bb1 : bb0);
                    float g = 0.5f * u * (1.f + erff(u * IS2));
                    int row = wm * 32 + mt * 16 + lr + ((e >> 1) << 3);
                    int col = colb + (e & 1);
                    gb[row * SROW + permk(col)] = tf32r(g);
                }
        }
        __syncthreads();

        for (int idx = tid; idx < 128 * 32; idx += 512) {
            int k = idx >> 5, o4 = (idx & 31) << 2;
            float4 w = *(const float4*)(W2 + (size_t)(n0 + k) * HID + o4);
            int kp = permk(k);
            wb[(o4 + 0) * SROW + kp] = tf32r(w.x);
            wb[(o4 + 1) * SROW + kp] = tf32r(w.y);
            wb[(o4 + 2) * SROW + kp] = tf32r(w.z);
            wb[(o4 + 3) * SROW + kp] = tf32r(w.w);
        }
        __syncthreads();

        warp_gemm2(gb + (wm * 32 + lr) * SROW + lc2,
                   wb + (wn * 32 + lr) * SROW + lc2, F);
    }
    __syncthreads();

#pragma unroll
    for (int nt = 0; nt < 4; nt++) {
        int col0 = wn * 32 + nt * 8 + lc2;
        float bb0 = b2[col0], bb1 = b2[col0 + 1];
#pragma unroll
        for (int mt = 0; mt < 2; mt++)
#pragma unroll
            for (int e = 0; e < 4; e++) {
                int row = wm * 32 + mt * 16 + lr + ((e >> 1) << 3);
                int col = col0 + (e & 1);
                float z = hs[row * SROW + permk(col)] + F[mt][nt][e]
                          + ((e & 1) ? bb1 : bb0);
                gb[row * SROW + col] = z;
            }
    }
    __syncthreads();

    for (int r = 0; r < 8; r++) {
        int row = warp * 8 + r, node = row0 + row;
        int c0 = lane * 4;
        float z0 = gb[row * SROW + c0];
        float z1 = gb[row * SROW + c0 + 1];
        float z2 = gb[row * SROW + c0 + 2];
        float z3 = gb[row * SROW + c0 + 3];
        float ss = z0 * z0 + z1 * z1 + z2 * z2 + z3 * z3;
#pragma unroll
        for (int o = 16; o > 0; o >>= 1) ss += __shfl_xor_sync(0xffffffffu, ss, o);
        float rs = rsqrtf(ss * (1.f / 128.f) + EPS);
        float4 w = ((const float4*)wn2)[lane];
        if (node < NN) {
            ((float4*)out)[node * 32 + lane] =
                make_float4(z0 * rs * w.x, z1 * rs * w.y,
                            z2 * rs * w.z, z3 * rs * w.w);
        }
    }
}

// ---------------- launch ---------------------------------------------------
extern "C" void kernel_launch(void* const* d_in, const int* in_sizes, int n_in,
                              void* d_out, int out_size) {
    const float* x        = (const float*)d_in[0];
    const int*   ei       = (const int*)  d_in[1];
    const float* ea       = (const float*)d_in[2];
    const float* Wl       = (const float*)d_in[3];
    const float* bl       = (const float*)d_in[4];
    const float* Wr       = (const float*)d_in[5];
    const float* br       = (const float*)d_in[6];
    const float* We       = (const float*)d_in[7];
    const float* att      = (const float*)d_in[8];
    const float* bias_gat = (const float*)d_in[9];
    const float* wn1      = (const float*)d_in[10];
    const float* wn2      = (const float*)d_in[11];
    const float* W1       = (const float*)d_in[12];
    const float* b1       = (const float*)d_in[13];
    const float* W2       = (const float*)d_in[14];
    const float* b2       = (const float*)d_in[15];
    float* out = (float*)d_out;

    const int SM1 = 2 * 128 * SROW * 4;   // 135168 B
    const int SM5 = 3 * 128 * SROW * 4;   // 202752 B
    cudaFuncSetAttribute(k1_mma, cudaFuncAttributeMaxDynamicSharedMemorySize, SM1);
    cudaFuncSetAttribute(k5_mma, cudaFuncAttributeMaxDynamicSharedMemorySize, SM5);

    const int NB = (NN + 127) / 128;      // 391

    k0_init<<<(NN + 255) / 256, 256>>>();
    kd_count<<<(EE + 255) / 256, 256>>>(ei);
    ks1<<<SCAN_B, 256>>>();
    ks2<<<1, 256>>>();
    ks3<<<SCAN_B, 256>>>();
    k_fill<<<(EE + 255) / 256, 256>>>(ei);
    k1_mma<<<NB, 512, SM1>>>(x, Wl, bl, Wr, br);
    k2_logits<<<EE / 8, 256>>>(ei, ea, We, att);
    k4_agg<<<(NN * 32 + 255) / 256, 256>>>();
    k5_mma<<<NB, 512, SM5>>>(x, bias_gat, wn1, W1, b1, W2, b2, wn2, out);
}